// round 11
// baseline (speedup 1.0000x reference)
#include <cuda_runtime.h>
#include <math.h>

#define BB 32
#define HH 512
#define WW 512
#define CC 3
#define RR 6              // truncated half-width (13 taps)
#define KK 13
#define TW 64             // tile width
#define TH 32             // tile height
#define HLR 44            // halo rows = TH + 2*RR
#define HLC 76            // halo cols = TW + 2*RR
#define SPITCH 84         // smem input pitch (floats, mult of 4)
#define HPITCH 68         // h-out pitch (floats, mult of 4)
#define NTH 512
#define EPS 1e-4f

// padded centered scratch: rows 6+512+6=524, row stride 528, origin (6,6).
// Borders never written -> stay zero (device globals are zero-initialized).
#define PH 524
#define PW 528

// 13-tap Gaussian(std=1) weights normalized by the full 19-tap sum.
#define WLIST { 6.0758833e-9f, 1.4867195e-6f, 1.3383022e-4f, 4.4318485e-3f, \
                5.3990967e-2f, 2.4197072e-1f, 3.9894228e-1f, 2.4197072e-1f, \
                5.3990967e-2f, 4.4318485e-3f, 1.3383022e-4f, 1.4867195e-6f, \
                6.0758833e-9f }

__device__ float g_cent[(size_t)BB * CC * PH * PW];

// ---------------------------------------------------------------------------
// Horizontal pass: 352 tasks = 8 col-groups x 44 rows, 8 outputs each.
// Task index: g = tid/44 (mul-shift), row = tid - 44*g -> warp lanes span
// consecutive ROWS of one group (row stride 336B: verified conflict-free).
// STAGED form (R8-proven): 5x LDS.128 into a[20], then 104 FFMA.
// ---------------------------------------------------------------------------
template<bool SQ>
__device__ __forceinline__ void hpass(const float* __restrict__ sin_,
                                      float* __restrict__ sh_, int tid) {
    const float W[KK] = WLIST;
    if (tid < HLR * 8) {
        int g   = (tid * 745) >> 15;      // tid / 44
        int row = tid - g * 44;
        const float4* sp = (const float4*)(sin_ + row * SPITCH) + g * 2;
        float a[20];
#pragma unroll
        for (int q = 0; q < 5; q++) {
            float4 v = sp[q];
            a[4*q+0] = v.x; a[4*q+1] = v.y; a[4*q+2] = v.z; a[4*q+3] = v.w;
        }
        if (SQ) {
#pragma unroll
            for (int k = 0; k < 20; k++) a[k] *= a[k];
        }
        float acc[8];
#pragma unroll
        for (int o = 0; o < 8; o++) acc[o] = 0.f;
#pragma unroll
        for (int k = 0; k < 20; k++) {
#pragma unroll
            for (int o = 0; o < 8; o++) {
                int j = k - o;
                if (j >= 0 && j < KK) acc[o] = fmaf(W[j], a[k], acc[o]);
            }
        }
        float4* op = (float4*)(sh_ + row * HPITCH) + g * 2;
        op[0] = make_float4(acc[0], acc[1], acc[2], acc[3]);
        op[1] = make_float4(acc[4], acc[5], acc[6], acc[7]);
    }
}

// ---------------------------------------------------------------------------
// Kernel 1: centered = x0 - blur(x0); writes interior of padded g_cent.
// ---------------------------------------------------------------------------
__global__ __launch_bounds__(NTH)
void lcn_mean_kernel(const float* __restrict__ xg) {
    __shared__ float sin_[HLR * SPITCH];
    __shared__ float sh_[HLR * HPITCH];
    const float W[KK] = WLIST;

    const int tx0 = blockIdx.x * TW;
    const int ty0 = blockIdx.y * TH;
    const int b   = blockIdx.z;
    const int tid  = threadIdx.x;
    const int warp = tid >> 5;
    const int lane = tid & 31;
    const int lx = tid & 63;
    const int yb = (tid >> 6) * 4;

    const float* xb = xg + (size_t)b * HH * WW * CC;
    const bool interior = (blockIdx.x >= 1) && (blockIdx.x <= 6) &&
                          (blockIdx.y >= 1) && (blockIdx.y <= 14);

#pragma unroll 1
    for (int c = 0; c < CC; c++) {
        if (interior) {
            // predicate-free halo load (deinterleave channel c)
            for (int row = warp; row < HLR; row += 16) {
                const float* rp = xb + ((size_t)(ty0 - RR + row) * WW + (tx0 - RR)) * CC + c;
                float* sp = sin_ + row * SPITCH;
                sp[lane]      = rp[3 * lane];
                sp[lane + 32] = rp[3 * (lane + 32)];
                if (lane < HLC - 64) sp[lane + 64] = rp[3 * (lane + 64)];
            }
        } else {
            for (int row = warp; row < HLR; row += 16) {
                int gy = ty0 - RR + row;
                bool rv = ((unsigned)gy < HH);
                const float* rp = xb + ((size_t)gy * WW + (tx0 - RR)) * CC + c;
                float* sp = sin_ + row * SPITCH;
#pragma unroll
                for (int s = 0; s < 3; s++) {
                    int xx = lane + s * 32;
                    if (xx < HLC) {
                        int gx = tx0 - RR + xx;
                        float v = 0.f;
                        if (rv && (unsigned)gx < WW) v = rp[3 * xx];
                        sp[xx] = v;
                    }
                }
            }
        }
        __syncthreads();

        hpass<false>(sin_, sh_, tid);
        __syncthreads();

        // vertical pass: column lx, rows yb..yb+3
        float acc0 = 0.f, acc1 = 0.f, acc2 = 0.f, acc3 = 0.f;
#pragma unroll
        for (int k = 0; k < KK + 3; k++) {
            float v = sh_[(yb + k) * HPITCH + lx];
            if (k - 0 >= 0 && k - 0 < KK) acc0 = fmaf(W[k - 0], v, acc0);
            if (k - 1 >= 0 && k - 1 < KK) acc1 = fmaf(W[k - 1], v, acc1);
            if (k - 2 >= 0 && k - 2 < KK) acc2 = fmaf(W[k - 2], v, acc2);
            if (k - 3 >= 0 && k - 3 < KK) acc3 = fmaf(W[k - 3], v, acc3);
        }
        // store to padded g_cent (origin 6,6), coalesced
        float* cb = g_cent + ((size_t)(b * CC + c) * PH + (ty0 + yb + RR)) * PW
                    + (tx0 + lx + RR);
        cb[0 * (size_t)PW] = sin_[(yb + 0 + RR) * SPITCH + lx + RR] - acc0;
        cb[1 * (size_t)PW] = sin_[(yb + 1 + RR) * SPITCH + lx + RR] - acc1;
        cb[2 * (size_t)PW] = sin_[(yb + 2 + RR) * SPITCH + lx + RR] - acc2;
        cb[3 * (size_t)PW] = sin_[(yb + 3 + RR) * SPITCH + lx + RR] - acc3;
        __syncthreads();
    }
}

// ---------------------------------------------------------------------------
// Kernel 2: var = blur(centered^2); out = centered/(sqrt(var)+eps) * mask
// ---------------------------------------------------------------------------
__global__ __launch_bounds__(NTH)
void lcn_out_kernel(const float* __restrict__ mask, float* __restrict__ out) {
    __shared__ float sin_[HLR * SPITCH];   // unsquared centered halo
    __shared__ float sh_[HLR * HPITCH];
    const float W[KK] = WLIST;

    const int tx0 = blockIdx.x * TW;
    const int ty0 = blockIdx.y * TH;
    const int b   = blockIdx.z;
    const int tid = threadIdx.x;
    const int lx = tid & 63;
    const int yb = (tid >> 6) * 4;

    float res[CC][4];

#pragma unroll 1
    for (int c = 0; c < CC; c++) {
        // halo load: pure float4 copies, no bounds checks (zero-padded gmem).
        // 44 rows x 19 float4 (76 floats) = 836 tasks, 2 iterations.
        for (int f = tid; f < HLR * 19; f += NTH) {
            int row = (f * 3450) >> 16;    // f / 19
            int seg = f - row * 19;
            const float4* gp = (const float4*)(g_cent +
                ((size_t)(b * CC + c) * PH + (ty0 + row)) * PW) + 16 * blockIdx.x;
            ((float4*)(sin_ + row * SPITCH))[seg] = gp[seg];
        }
        __syncthreads();

        hpass<true>(sin_, sh_, tid);   // squares on the fly
        __syncthreads();

        // vertical pass -> var -> res
        float acc0 = 0.f, acc1 = 0.f, acc2 = 0.f, acc3 = 0.f;
#pragma unroll
        for (int k = 0; k < KK + 3; k++) {
            float v = sh_[(yb + k) * HPITCH + lx];
            if (k - 0 >= 0 && k - 0 < KK) acc0 = fmaf(W[k - 0], v, acc0);
            if (k - 1 >= 0 && k - 1 < KK) acc1 = fmaf(W[k - 1], v, acc1);
            if (k - 2 >= 0 && k - 2 < KK) acc2 = fmaf(W[k - 2], v, acc2);
            if (k - 3 >= 0 && k - 3 < KK) acc3 = fmaf(W[k - 3], v, acc3);
        }
        res[c][0] = __fdividef(sin_[(yb + 0 + RR) * SPITCH + lx + RR], sqrtf(acc0) + EPS);
        res[c][1] = __fdividef(sin_[(yb + 1 + RR) * SPITCH + lx + RR], sqrtf(acc1) + EPS);
        res[c][2] = __fdividef(sin_[(yb + 2 + RR) * SPITCH + lx + RR], sqrtf(acc2) + EPS);
        res[c][3] = __fdividef(sin_[(yb + 3 + RR) * SPITCH + lx + RR], sqrtf(acc3) + EPS);
        __syncthreads();
    }

    // mask + interleaved output
#pragma unroll
    for (int r = 0; r < 4; r++) {
        int gy = ty0 + yb + r;
        int gx = tx0 + lx;
        float m = mask[(size_t)(b * HH + gy) * WW + gx];
        size_t o = ((size_t)(b * HH + gy) * WW + gx) * CC;
        out[o + 0] = res[0][r] * m;
        out[o + 1] = res[1][r] * m;
        out[o + 2] = res[2][r] * m;
    }
}

// ---------------------------------------------------------------------------
extern "C" void kernel_launch(void* const* d_in, const int* in_sizes, int n_in,
                              void* d_out, int out_size) {
    const float* x0   = (const float*)d_in[0];
    const float* mask = (const float*)d_in[1];
    float* out = (float*)d_out;

    dim3 grid(WW / TW, HH / TH, BB);
    lcn_mean_kernel<<<grid, NTH>>>(x0);
    lcn_out_kernel<<<grid, NTH>>>(mask, out);
}

// round 12
// speedup vs baseline: 1.0488x; 1.0488x over previous
#include <cuda_runtime.h>
#include <math.h>

#define BB 32
#define HH 512
#define WW 512
#define RR 6               // truncated half-width (13 taps)
#define KK 13
#define TT 32              // tile (32x32)
#define HLR 44             // halo rows/cols = TT + 2*RR
#define SP3 140            // interleaved smem pitch (floats); 140%32=12 -> conflict-free
#define HP3 36             // h-out pitch per channel
#define SH3CH (HLR * HP3)  // 1584 floats per channel
#define NTH 256
#define EPS 1e-4f

// interleaved padded centered scratch: [B][524 rows][528 px * 3 floats]
// rows/cols 0..5 and 518.. are border, never written -> stay zero.
#define PH 524
#define PWF 1584           // 528 px * 3 floats per padded row

// 13-tap Gaussian(std=1) weights normalized by the full 19-tap sum.
#define WLIST { 6.0758833e-9f, 1.4867195e-6f, 1.3383022e-4f, 4.4318485e-3f, \
                5.3990967e-2f, 2.4197072e-1f, 3.9894228e-1f, 2.4197072e-1f, \
                5.3990967e-2f, 4.4318485e-3f, 1.3383022e-4f, 1.4867195e-6f, \
                6.0758833e-9f }

__device__ float g_cent[(size_t)BB * PH * PWF];

// ---------------------------------------------------------------------------
// 3-channel horizontal pass over interleaved smem.
// Task (row, g): 8 output cols x 3 channels. Local float index of halo px p,
// channel c is 3p + XOFF + c. Reads NSEG float4 starting at float 24g
// (XOFF=2, k1) or 24g aligned with XOFF=0 (k2). (pixel,channel) of each
// loaded float is compile-time: fo = 4s+u-XOFF -> d = fo/3, ch = fo%3.
// ---------------------------------------------------------------------------
template<int XOFF, int NSEG, bool SQ>
__device__ __forceinline__ void hpass3(const float* __restrict__ si3,
                                       float* __restrict__ sh3, int tid) {
    const float W[KK] = WLIST;
    int row = tid >> 2;
    int g   = tid & 3;
    if (row < HLR) {
        const float4* sp = (const float4*)(si3 + row * SP3 + 24 * g);
        float acc[3][8];
#pragma unroll
        for (int ch = 0; ch < 3; ch++)
#pragma unroll
            for (int o = 0; o < 8; o++) acc[ch][o] = 0.f;
#pragma unroll
        for (int s = 0; s < NSEG; s++) {
            float4 v4 = sp[s];
            float vv[4] = {v4.x, v4.y, v4.z, v4.w};
#pragma unroll
            for (int u = 0; u < 4; u++) {
                int fo = 4 * s + u - XOFF;
                if (fo >= 0 && fo < 60) {        // d = 0..19
                    int d  = fo / 3;
                    int ch = fo % 3;
                    float v = SQ ? vv[u] * vv[u] : vv[u];
#pragma unroll
                    for (int oo = 0; oo < 8; oo++) {
                        int j = d - oo;
                        if (j >= 0 && j < KK)
                            acc[ch][oo] = fmaf(W[j], v, acc[ch][oo]);
                    }
                }
            }
        }
#pragma unroll
        for (int ch = 0; ch < 3; ch++) {
            float4* op = (float4*)(sh3 + ch * SH3CH + row * HP3 + 8 * g);
            op[0] = make_float4(acc[ch][0], acc[ch][1], acc[ch][2], acc[ch][3]);
            op[1] = make_float4(acc[ch][4], acc[ch][5], acc[ch][6], acc[ch][7]);
        }
    }
}

// ---------------------------------------------------------------------------
// Kernel 1: centered = x0 - blur(x0); writes interior of interleaved g_cent.
// ---------------------------------------------------------------------------
__global__ __launch_bounds__(NTH, 5)
void lcn_mean_kernel(const float* __restrict__ xg) {
    __shared__ float si3[HLR * SP3];        // interleaved x halo
    __shared__ float sh3[3 * SH3CH];        // per-channel h-blur
    const float W[KK] = WLIST;

    const int tx0 = blockIdx.x * TT;
    const int ty0 = blockIdx.y * TT;
    const int b   = blockIdx.z;
    const int tid = threadIdx.x;

    const bool interior = (blockIdx.x >= 1) && (blockIdx.x <= 14) &&
                          (blockIdx.y >= 1) && (blockIdx.y <= 14);

    // ---- halo load: global float base of row = 3*tx0-20 (16B aligned).
    // local float f corresponds to px p=(f-2)/3, ch=(f-2)%3  (XOFF=2).
    const int gbase = 3 * tx0 - 20;
    if (interior) {
        for (int m = tid; m < HLR * 34; m += NTH) {
            int row = m / 34;
            int seg = m - row * 34;
            const float4* gp = (const float4*)(xg +
                ((size_t)(b * HH + ty0 - RR + row) * WW) * 3 + gbase) + seg;
            ((float4*)(si3 + row * SP3))[seg] = *gp;
        }
    } else {
        for (int m = tid; m < HLR * 136; m += NTH) {
            int row = m / 136;
            int f   = m - row * 136;
            int gy  = ty0 - RR + row;
            int gf  = gbase + f;
            float v = 0.f;
            if ((unsigned)gy < HH && (unsigned)gf < 3 * WW)
                v = xg[((size_t)(b * HH + gy) * WW) * 3 + gf];
            si3[row * SP3 + f] = v;
        }
    }
    __syncthreads();

    hpass3<2, 16, false>(si3, sh3, tid);
    __syncthreads();

    // ---- vertical pass (all 3 channels) -> centered -> g_cent
    const int lx = tid & 31;
    const int yb = (tid >> 5) * 4;
#pragma unroll
    for (int c = 0; c < 3; c++) {
        float acc0 = 0.f, acc1 = 0.f, acc2 = 0.f, acc3 = 0.f;
        const float* bp = sh3 + c * SH3CH + yb * HP3 + lx;
#pragma unroll
        for (int k = 0; k < KK + 3; k++) {
            float v = bp[k * HP3];
            if (k - 0 >= 0 && k - 0 < KK) acc0 = fmaf(W[k - 0], v, acc0);
            if (k - 1 >= 0 && k - 1 < KK) acc1 = fmaf(W[k - 1], v, acc1);
            if (k - 2 >= 0 && k - 2 < KK) acc2 = fmaf(W[k - 2], v, acc2);
            if (k - 3 >= 0 && k - 3 < KK) acc3 = fmaf(W[k - 3], v, acc3);
        }
        float accs[4] = {acc0, acc1, acc2, acc3};
#pragma unroll
        for (int r = 0; r < 4; r++) {
            float xv = si3[(yb + r + RR) * SP3 + 3 * lx + 20 + c];
            g_cent[((size_t)b * PH + (ty0 + yb + r + RR)) * PWF
                   + (size_t)(tx0 + lx + RR) * 3 + c] = xv - accs[r];
        }
    }
}

// ---------------------------------------------------------------------------
// Kernel 2: var = blur(centered^2); out = centered/(sqrt(var)+eps) * mask
// ---------------------------------------------------------------------------
__global__ __launch_bounds__(NTH, 5)
void lcn_out_kernel(const float* __restrict__ mask, float* __restrict__ out) {
    __shared__ float si3[HLR * SP3];        // interleaved centered halo
    __shared__ float sh3[3 * SH3CH];
    const float W[KK] = WLIST;

    const int tx0 = blockIdx.x * TT;
    const int ty0 = blockIdx.y * TT;
    const int b   = blockIdx.z;
    const int tid = threadIdx.x;

    // ---- halo: 44 rows x 33 float4, aligned (3*tx0 % 4 == 0), no bounds
    // checks (padded borders are zero). local float f: px p=f/3, ch=f%3.
    for (int m = tid; m < HLR * 33; m += NTH) {
        int row = m / 33;
        int seg = m - row * 33;
        const float4* gp = (const float4*)(g_cent +
            ((size_t)b * PH + ty0 + row) * PWF + 3 * tx0) + seg;
        ((float4*)(si3 + row * SP3))[seg] = *gp;
    }
    __syncthreads();

    hpass3<0, 15, true>(si3, sh3, tid);   // squares on the fly
    __syncthreads();

    // ---- vertical pass -> var -> out (all 3 channels)
    const int lx = tid & 31;
    const int yb = (tid >> 5) * 4;
    float res[3][4];
#pragma unroll
    for (int c = 0; c < 3; c++) {
        float acc0 = 0.f, acc1 = 0.f, acc2 = 0.f, acc3 = 0.f;
        const float* bp = sh3 + c * SH3CH + yb * HP3 + lx;
#pragma unroll
        for (int k = 0; k < KK + 3; k++) {
            float v = bp[k * HP3];
            if (k - 0 >= 0 && k - 0 < KK) acc0 = fmaf(W[k - 0], v, acc0);
            if (k - 1 >= 0 && k - 1 < KK) acc1 = fmaf(W[k - 1], v, acc1);
            if (k - 2 >= 0 && k - 2 < KK) acc2 = fmaf(W[k - 2], v, acc2);
            if (k - 3 >= 0 && k - 3 < KK) acc3 = fmaf(W[k - 3], v, acc3);
        }
        float accs[4] = {acc0, acc1, acc2, acc3};
#pragma unroll
        for (int r = 0; r < 4; r++) {
            float cv = si3[(yb + r + RR) * SP3 + 3 * lx + 18 + c];
            res[c][r] = __fdividef(cv, sqrtf(accs[r]) + EPS);
        }
    }

    // ---- mask + interleaved output
#pragma unroll
    for (int r = 0; r < 4; r++) {
        int gy = ty0 + yb + r;
        int gx = tx0 + lx;
        float m = mask[(size_t)(b * HH + gy) * WW + gx];
        size_t o = ((size_t)(b * HH + gy) * WW + gx) * 3;
        out[o + 0] = res[0][r] * m;
        out[o + 1] = res[1][r] * m;
        out[o + 2] = res[2][r] * m;
    }
}

// ---------------------------------------------------------------------------
extern "C" void kernel_launch(void* const* d_in, const int* in_sizes, int n_in,
                              void* d_out, int out_size) {
    const float* x0   = (const float*)d_in[0];
    const float* mask = (const float*)d_in[1];
    float* out = (float*)d_out;

    dim3 grid(WW / TT, HH / TT, BB);
    lcn_mean_kernel<<<grid, NTH>>>(x0);
    lcn_out_kernel<<<grid, NTH>>>(mask, out);
}

// round 15
// speedup vs baseline: 1.1722x; 1.1177x over previous
#include <cuda_runtime.h>
#include <cstdint>
#include <math.h>

#define BB 32
#define HH 512
#define WW 512
#define RR 6               // truncated half-width (13 taps)
#define KK 13
#define TT 32              // tile (32x32)
#define HLR 44             // halo rows/cols = TT + 2*RR
#define SP3 140            // interleaved smem pitch (floats); 140%32=12 -> conflict-free
#define HP3 36             // h-out pitch per channel
#define SH3CH (HLR * HP3)  // 1584 floats per channel
#define NTH 256
#define EPS 1e-4f

// interleaved padded centered scratch: [B][524 rows][528 px * 3 floats]
// rows/cols 0..5 and 518.. are border, never written -> stay zero.
#define PH 524
#define PWF 1584           // 528 px * 3 floats per padded row

// 13-tap Gaussian(std=1) weights normalized by the full 19-tap sum.
#define WLIST { 6.0758833e-9f, 1.4867195e-6f, 1.3383022e-4f, 4.4318485e-3f, \
                5.3990967e-2f, 2.4197072e-1f, 3.9894228e-1f, 2.4197072e-1f, \
                5.3990967e-2f, 4.4318485e-3f, 1.3383022e-4f, 1.4867195e-6f, \
                6.0758833e-9f }

__device__ float g_cent[(size_t)BB * PH * PWF];

#define CP_ASYNC16(dst_u32, src_ptr) \
    asm volatile("cp.async.ca.shared.global [%0], [%1], 16;" \
                 :: "r"(dst_u32), "l"(src_ptr))
#define CP_COMMIT()  asm volatile("cp.async.commit_group;")
#define CP_WAIT0()   asm volatile("cp.async.wait_group 0;")

// ---------------------------------------------------------------------------
// 3-channel horizontal pass over interleaved smem.
// Task (row, g): 8 output cols x 3 channels. Local float index of halo px p,
// channel c is 3p + XOFF + c. (pixel,channel) decode of each loaded float is
// compile-time: fo = 4s+u-XOFF -> d = fo/3, ch = fo%3.
// ---------------------------------------------------------------------------
template<int XOFF, int NSEG, bool SQ>
__device__ __forceinline__ void hpass3(const float* __restrict__ si3,
                                       float* __restrict__ sh3, int tid) {
    const float W[KK] = WLIST;
    int row = tid >> 2;
    int g   = tid & 3;
    if (row < HLR) {
        const float4* sp = (const float4*)(si3 + row * SP3 + 24 * g);
        float acc[3][8];
#pragma unroll
        for (int ch = 0; ch < 3; ch++)
#pragma unroll
            for (int o = 0; o < 8; o++) acc[ch][o] = 0.f;
#pragma unroll
        for (int s = 0; s < NSEG; s++) {
            float4 v4 = sp[s];
            float vv[4] = {v4.x, v4.y, v4.z, v4.w};
#pragma unroll
            for (int u = 0; u < 4; u++) {
                int fo = 4 * s + u - XOFF;
                if (fo >= 0 && fo < 60) {        // d = 0..19
                    int d  = fo / 3;
                    int ch = fo % 3;
                    float v = SQ ? vv[u] * vv[u] : vv[u];
#pragma unroll
                    for (int oo = 0; oo < 8; oo++) {
                        int j = d - oo;
                        if (j >= 0 && j < KK)
                            acc[ch][oo] = fmaf(W[j], v, acc[ch][oo]);
                    }
                }
            }
        }
#pragma unroll
        for (int ch = 0; ch < 3; ch++) {
            float4* op = (float4*)(sh3 + ch * SH3CH + row * HP3 + 8 * g);
            op[0] = make_float4(acc[ch][0], acc[ch][1], acc[ch][2], acc[ch][3]);
            op[1] = make_float4(acc[ch][4], acc[ch][5], acc[ch][6], acc[ch][7]);
        }
    }
}

// ---------------------------------------------------------------------------
// Kernel 1: centered = x0 - blur(x0); writes interior of interleaved g_cent.
// ---------------------------------------------------------------------------
__global__ __launch_bounds__(NTH, 5)
void lcn_mean_kernel(const float* __restrict__ xg) {
    __shared__ float si3[HLR * SP3];        // interleaved x halo
    __shared__ float sh3[3 * SH3CH];        // per-channel h-blur
    const float W[KK] = WLIST;

    const int tx0 = blockIdx.x * TT;
    const int ty0 = blockIdx.y * TT;
    const int b   = blockIdx.z;
    const int tid = threadIdx.x;

    const bool interior = (blockIdx.x >= 1) && (blockIdx.x <= 14) &&
                          (blockIdx.y >= 1) && (blockIdx.y <= 14);

    // ---- halo load: global float base of row = 3*tx0-20 (16B aligned).
    // local float f corresponds to px p=(f-2)/3, ch=(f-2)%3  (XOFF=2).
    const int gbase = 3 * tx0 - 20;
    if (interior) {
        const uint32_t s0 = (uint32_t)__cvta_generic_to_shared(si3);
        const float* g0 = xg + (size_t)(b * HH + ty0 - RR) * (WW * 3) + gbase;
        for (int m = tid; m < HLR * 34; m += NTH) {          // 1496 segs
            int row = (m * 1928) >> 16;                      // m / 34
            int seg = m - row * 34;
            uint32_t dst = s0 + (uint32_t)(row * SP3 + seg * 4) * 4u;
            CP_ASYNC16(dst, g0 + row * (WW * 3) + seg * 4);
        }
        CP_COMMIT();
        CP_WAIT0();
    } else {
        const float* g0 = xg + (size_t)b * HH * (WW * 3);
        for (int m = tid; m < HLR * 136; m += NTH) {
            int row = m / 136;
            int f   = m - row * 136;
            int gy  = ty0 - RR + row;
            int gf  = gbase + f;
            float v = 0.f;
            if ((unsigned)gy < HH && (unsigned)gf < 3 * WW)
                v = g0[(size_t)gy * (WW * 3) + gf];
            si3[row * SP3 + f] = v;
        }
    }
    __syncthreads();

    hpass3<2, 16, false>(si3, sh3, tid);
    __syncthreads();

    // ---- vertical pass (all 3 channels) -> centered -> g_cent
    const int lx = tid & 31;
    const int yb = (tid >> 5) * 4;
    float* cb0 = g_cent + ((size_t)b * PH + (ty0 + yb + RR)) * PWF
                 + (size_t)(tx0 + lx + RR) * 3;
#pragma unroll
    for (int c = 0; c < 3; c++) {
        float acc0 = 0.f, acc1 = 0.f, acc2 = 0.f, acc3 = 0.f;
        const float* bp = sh3 + c * SH3CH + yb * HP3 + lx;
#pragma unroll
        for (int k = 0; k < KK + 3; k++) {
            float v = bp[k * HP3];
            if (k - 0 >= 0 && k - 0 < KK) acc0 = fmaf(W[k - 0], v, acc0);
            if (k - 1 >= 0 && k - 1 < KK) acc1 = fmaf(W[k - 1], v, acc1);
            if (k - 2 >= 0 && k - 2 < KK) acc2 = fmaf(W[k - 2], v, acc2);
            if (k - 3 >= 0 && k - 3 < KK) acc3 = fmaf(W[k - 3], v, acc3);
        }
        float accs[4] = {acc0, acc1, acc2, acc3};
#pragma unroll
        for (int r = 0; r < 4; r++) {
            float xv = si3[(yb + r + RR) * SP3 + 3 * lx + 20 + c];
            cb0[r * PWF + c] = xv - accs[r];
        }
    }
}

// ---------------------------------------------------------------------------
// Kernel 2: var = blur(centered^2); out = centered/(sqrt(var)+eps) * mask
// ---------------------------------------------------------------------------
__global__ __launch_bounds__(NTH, 5)
void lcn_out_kernel(const float* __restrict__ mask, float* __restrict__ out) {
    __shared__ float si3[HLR * SP3];        // interleaved centered halo
    __shared__ float sh3[3 * SH3CH];
    const float W[KK] = WLIST;

    const int tx0 = blockIdx.x * TT;
    const int ty0 = blockIdx.y * TT;
    const int b   = blockIdx.z;
    const int tid = threadIdx.x;

    // ---- halo: 44 rows x 33 float4, aligned, no bounds checks (padded
    // borders are zero), via cp.async. local float f: px p=f/3, ch=f%3.
    {
        const uint32_t s0 = (uint32_t)__cvta_generic_to_shared(si3);
        const float* g0 = g_cent + ((size_t)b * PH + ty0) * PWF + 3 * tx0;
        for (int m = tid; m < HLR * 33; m += NTH) {          // 1452 segs
            int row = (m * 1986) >> 16;                      // m / 33
            int seg = m - row * 33;
            uint32_t dst = s0 + (uint32_t)(row * SP3 + seg * 4) * 4u;
            CP_ASYNC16(dst, g0 + row * PWF + seg * 4);
        }
        CP_COMMIT();
        CP_WAIT0();
    }
    __syncthreads();

    hpass3<0, 15, true>(si3, sh3, tid);   // squares on the fly
    __syncthreads();

    // ---- vertical pass -> var -> out (all 3 channels)
    const int lx = tid & 31;
    const int yb = (tid >> 5) * 4;
    float res[3][4];
#pragma unroll
    for (int c = 0; c < 3; c++) {
        float acc0 = 0.f, acc1 = 0.f, acc2 = 0.f, acc3 = 0.f;
        const float* bp = sh3 + c * SH3CH + yb * HP3 + lx;
#pragma unroll
        for (int k = 0; k < KK + 3; k++) {
            float v = bp[k * HP3];
            if (k - 0 >= 0 && k - 0 < KK) acc0 = fmaf(W[k - 0], v, acc0);
            if (k - 1 >= 0 && k - 1 < KK) acc1 = fmaf(W[k - 1], v, acc1);
            if (k - 2 >= 0 && k - 2 < KK) acc2 = fmaf(W[k - 2], v, acc2);
            if (k - 3 >= 0 && k - 3 < KK) acc3 = fmaf(W[k - 3], v, acc3);
        }
        float accs[4] = {acc0, acc1, acc2, acc3};
#pragma unroll
        for (int r = 0; r < 4; r++) {
            float cv = si3[(yb + r + RR) * SP3 + 3 * lx + 18 + c];
            res[c][r] = __fdividef(cv, sqrtf(accs[r]) + EPS);
        }
    }

    // ---- mask + interleaved output
    const float* mrow = mask + (size_t)(b * HH + ty0 + yb) * WW + tx0 + lx;
    float* orow = out + ((size_t)(b * HH + ty0 + yb) * WW + tx0 + lx) * 3;
#pragma unroll
    for (int r = 0; r < 4; r++) {
        float m = mrow[(size_t)r * WW];
        float* op = orow + (size_t)r * WW * 3;
        op[0] = res[0][r] * m;
        op[1] = res[1][r] * m;
        op[2] = res[2][r] * m;
    }
}

// ---------------------------------------------------------------------------
extern "C" void kernel_launch(void* const* d_in, const int* in_sizes, int n_in,
                              void* d_out, int out_size) {
    const float* x0   = (const float*)d_in[0];
    const float* mask = (const float*)d_in[1];
    float* out = (float*)d_out;

    dim3 grid(WW / TT, HH / TT, BB);
    lcn_mean_kernel<<<grid, NTH>>>(x0);
    lcn_out_kernel<<<grid, NTH>>>(mask, out);
}

// round 17
// speedup vs baseline: 1.2012x; 1.0247x over previous
#include <cuda_runtime.h>
#include <cstdint>
#include <math.h>

#define BB 32
#define HH 512
#define WW 512
#define RR 6               // truncated half-width (13 taps)
#define KK 13
#define TT 32              // tile (32x32)
#define HLR 44             // halo rows/cols = TT + 2*RR
#define SP3 140            // interleaved smem pitch (floats); 140%32=12 -> conflict-free
#define HP3 36             // h-out pitch per channel
#define SH3CH (HLR * HP3)  // 1584 floats per channel
#define NTH 256
#define EPS 1e-4f

// interleaved padded centered scratch: [B][524 rows][528 px * 3 floats]
// rows/cols 0..5 and 518.. are border, never written -> stay zero.
#define PH 524
#define PWF 1584           // 528 px * 3 floats per padded row

// 13-tap Gaussian(std=1) weights normalized by the full 19-tap sum.
#define WLIST { 6.0758833e-9f, 1.4867195e-6f, 1.3383022e-4f, 4.4318485e-3f, \
                5.3990967e-2f, 2.4197072e-1f, 3.9894228e-1f, 2.4197072e-1f, \
                5.3990967e-2f, 4.4318485e-3f, 1.3383022e-4f, 1.4867195e-6f, \
                6.0758833e-9f }

__device__ float g_cent[(size_t)BB * PH * PWF];

#define CP_ASYNC16(dst_u32, src_ptr) \
    asm volatile("cp.async.ca.shared.global [%0], [%1], 16;" \
                 :: "r"(dst_u32), "l"(src_ptr))
#define CP_COMMIT()  asm volatile("cp.async.commit_group;")
#define CP_WAIT0()   asm volatile("cp.async.wait_group 0;")

// ---------------------------------------------------------------------------
// 3-channel horizontal pass over interleaved smem.
// Task (row, g): 8 output cols x 3 channels. Local float index of halo px p,
// channel c is 3p + XOFF + c. (pixel,channel) decode of each loaded float is
// compile-time: fo = 4s+u-XOFF -> d = fo/3, ch = fo%3.
// ---------------------------------------------------------------------------
template<int XOFF, int NSEG, bool SQ>
__device__ __forceinline__ void hpass3(const float* __restrict__ si3,
                                       float* __restrict__ sh3, int tid) {
    const float W[KK] = WLIST;
    int row = tid >> 2;
    int g   = tid & 3;
    if (row < HLR) {
        const float4* sp = (const float4*)(si3 + row * SP3 + 24 * g);
        float acc[3][8];
#pragma unroll
        for (int ch = 0; ch < 3; ch++)
#pragma unroll
            for (int o = 0; o < 8; o++) acc[ch][o] = 0.f;
#pragma unroll
        for (int s = 0; s < NSEG; s++) {
            float4 v4 = sp[s];
            float vv[4] = {v4.x, v4.y, v4.z, v4.w};
#pragma unroll
            for (int u = 0; u < 4; u++) {
                int fo = 4 * s + u - XOFF;
                if (fo >= 0 && fo < 60) {        // d = 0..19
                    int d  = fo / 3;
                    int ch = fo % 3;
                    float v = SQ ? vv[u] * vv[u] : vv[u];
#pragma unroll
                    for (int oo = 0; oo < 8; oo++) {
                        int j = d - oo;
                        if (j >= 0 && j < KK)
                            acc[ch][oo] = fmaf(W[j], v, acc[ch][oo]);
                    }
                }
            }
        }
#pragma unroll
        for (int ch = 0; ch < 3; ch++) {
            float4* op = (float4*)(sh3 + ch * SH3CH + row * HP3 + 8 * g);
            op[0] = make_float4(acc[ch][0], acc[ch][1], acc[ch][2], acc[ch][3]);
            op[1] = make_float4(acc[ch][4], acc[ch][5], acc[ch][6], acc[ch][7]);
        }
    }
}

// ---------------------------------------------------------------------------
// Kernel 1: centered = x0 - blur(x0); writes interior of interleaved g_cent.
// ---------------------------------------------------------------------------
__global__ __launch_bounds__(NTH, 5)
void lcn_mean_kernel(const float* __restrict__ xg) {
    __shared__ float si3[HLR * SP3];        // interleaved x halo
    __shared__ float sh3[3 * SH3CH];        // per-channel h-blur
    const float W[KK] = WLIST;

    const int tx0 = blockIdx.x * TT;
    const int ty0 = blockIdx.y * TT;
    const int b   = blockIdx.z;
    const int tid = threadIdx.x;

    // ---- unified halo load via predicated cp.async.
    // Row base float index = 3*tx0 - 20 (16B aligned). OOB geometry aligns
    // exactly with 16B segments:
    //   bx==0  -> segs 0..4 fully OOB (floats -20..-1)
    //   bx==15 -> segs 29..33 fully OOB (gf >= 1536)
    //   by==0  -> rows 0..5 OOB;  by==15 -> rows 38..43 OOB
    {
        const int slo = (blockIdx.x == 0)  ? 5        : 0;
        const int shi = (blockIdx.x == 15) ? 29       : 34;
        const int rlo = (blockIdx.y == 0)  ? RR       : 0;
        const int rhi = (blockIdx.y == 15) ? HLR - RR : HLR;
        const uint32_t s0 = (uint32_t)__cvta_generic_to_shared(si3);
        const float* g0 = xg + (size_t)(b * HH + ty0 - RR) * (WW * 3)
                          + (3 * tx0 - 20);
        const float4 z4 = make_float4(0.f, 0.f, 0.f, 0.f);
#pragma unroll
        for (int i = 0; i < 6; i++) {
            int m = tid + i * NTH;
            if (m < HLR * 34) {                          // 1496 segs
                int row = (m * 1928) >> 16;              // m / 34
                int seg = m - row * 34;
                if (row >= rlo && row < rhi && seg >= slo && seg < shi) {
                    uint32_t dst = s0 + (uint32_t)(row * SP3 + seg * 4) * 4u;
                    CP_ASYNC16(dst, g0 + row * (WW * 3) + seg * 4);
                } else {
                    ((float4*)(si3 + row * SP3))[seg] = z4;
                }
            }
        }
        CP_COMMIT();
        CP_WAIT0();
    }
    __syncthreads();

    hpass3<2, 16, false>(si3, sh3, tid);
    __syncthreads();

    // ---- vertical pass (all 3 channels) -> centered -> g_cent
    const int lx = tid & 31;
    const int yb = (tid >> 5) * 4;
    float* cb0 = g_cent + ((size_t)b * PH + (ty0 + yb + RR)) * PWF
                 + (size_t)(tx0 + lx + RR) * 3;
#pragma unroll
    for (int c = 0; c < 3; c++) {
        float acc0 = 0.f, acc1 = 0.f, acc2 = 0.f, acc3 = 0.f;
        const float* bp = sh3 + c * SH3CH + yb * HP3 + lx;
#pragma unroll
        for (int k = 0; k < KK + 3; k++) {
            float v = bp[k * HP3];
            if (k - 0 >= 0 && k - 0 < KK) acc0 = fmaf(W[k - 0], v, acc0);
            if (k - 1 >= 0 && k - 1 < KK) acc1 = fmaf(W[k - 1], v, acc1);
            if (k - 2 >= 0 && k - 2 < KK) acc2 = fmaf(W[k - 2], v, acc2);
            if (k - 3 >= 0 && k - 3 < KK) acc3 = fmaf(W[k - 3], v, acc3);
        }
        float accs[4] = {acc0, acc1, acc2, acc3};
#pragma unroll
        for (int r = 0; r < 4; r++) {
            float xv = si3[(yb + r + RR) * SP3 + 3 * lx + 20 + c];
            cb0[r * PWF + c] = xv - accs[r];
        }
    }
}

// ---------------------------------------------------------------------------
// Kernel 2: var = blur(centered^2); out = centered/(sqrt(var)+eps) * mask
// ---------------------------------------------------------------------------
__global__ __launch_bounds__(NTH, 5)
void lcn_out_kernel(const float* __restrict__ mask, float* __restrict__ out) {
    __shared__ float si3[HLR * SP3];        // interleaved centered halo
    __shared__ float sh3[3 * SH3CH];
    const float W[KK] = WLIST;

    const int tx0 = blockIdx.x * TT;
    const int ty0 = blockIdx.y * TT;
    const int b   = blockIdx.z;
    const int tid = threadIdx.x;
    const int lx = tid & 31;
    const int yb = (tid >> 5) * 4;

    // ---- issue halo cp.async first (44 rows x 33 float4, aligned, no bounds
    // checks: padded borders are zero). local float f: px p=f/3, ch=f%3.
    {
        const uint32_t s0 = (uint32_t)__cvta_generic_to_shared(si3);
        const float* g0 = g_cent + ((size_t)b * PH + ty0) * PWF + 3 * tx0;
#pragma unroll
        for (int i = 0; i < 6; i++) {
            int m = tid + i * NTH;
            if (m < HLR * 33) {                          // 1452 segs
                int row = (m * 1986) >> 16;              // m / 33
                int seg = m - row * 33;
                uint32_t dst = s0 + (uint32_t)(row * SP3 + seg * 4) * 4u;
                CP_ASYNC16(dst, g0 + row * PWF + seg * 4);
            }
        }
        CP_COMMIT();
    }

    // ---- prefetch mask while the halo is in flight (independent loads)
    const float* mrow = mask + (size_t)(b * HH + ty0 + yb) * WW + tx0 + lx;
    float mreg[4];
#pragma unroll
    for (int r = 0; r < 4; r++) mreg[r] = mrow[(size_t)r * WW];

    CP_WAIT0();
    __syncthreads();

    hpass3<0, 15, true>(si3, sh3, tid);   // squares on the fly
    __syncthreads();

    // ---- vertical pass -> var -> out (all 3 channels)
    float res[3][4];
#pragma unroll
    for (int c = 0; c < 3; c++) {
        float acc0 = 0.f, acc1 = 0.f, acc2 = 0.f, acc3 = 0.f;
        const float* bp = sh3 + c * SH3CH + yb * HP3 + lx;
#pragma unroll
        for (int k = 0; k < KK + 3; k++) {
            float v = bp[k * HP3];
            if (k - 0 >= 0 && k - 0 < KK) acc0 = fmaf(W[k - 0], v, acc0);
            if (k - 1 >= 0 && k - 1 < KK) acc1 = fmaf(W[k - 1], v, acc1);
            if (k - 2 >= 0 && k - 2 < KK) acc2 = fmaf(W[k - 2], v, acc2);
            if (k - 3 >= 0 && k - 3 < KK) acc3 = fmaf(W[k - 3], v, acc3);
        }
        float accs[4] = {acc0, acc1, acc2, acc3};
#pragma unroll
        for (int r = 0; r < 4; r++) {
            float cv = si3[(yb + r + RR) * SP3 + 3 * lx + 18 + c];
            res[c][r] = __fdividef(cv, sqrtf(accs[r]) + EPS);
        }
    }

    // ---- mask + interleaved output
    float* orow = out + ((size_t)(b * HH + ty0 + yb) * WW + tx0 + lx) * 3;
#pragma unroll
    for (int r = 0; r < 4; r++) {
        float m = mreg[r];
        float* op = orow + (size_t)r * WW * 3;
        op[0] = res[0][r] * m;
        op[1] = res[1][r] * m;
        op[2] = res[2][r] * m;
    }
}

// ---------------------------------------------------------------------------
extern "C" void kernel_launch(void* const* d_in, const int* in_sizes, int n_in,
                              void* d_out, int out_size) {
    const float* x0   = (const float*)d_in[0];
    const float* mask = (const float*)d_in[1];
    float* out = (float*)d_out;

    dim3 grid(WW / TT, HH / TT, BB);
    lcn_mean_kernel<<<grid, NTH>>>(x0);
    lcn_out_kernel<<<grid, NTH>>>(mask, out);
}